// round 15
// baseline (speedup 1.0000x reference)
#include <cuda_runtime.h>
#include <cstdint>
#include <math.h>

#define BB 4
#define SS 2048
#define DD 1024

#define TM 128
#define TN 64
#define TK 32
#define NTHREADS 256
#define STAGES 2
#define STAGE_BYTES 24576            // A fp32 16K | B fp32 8K
#define DSM_BYTES (STAGES * STAGE_BYTES + 1024)

// live score tiles per batch: sum_{by=0}^{15} 2(by+1) = 272
#define LIVE_TILES 272

// ---------------------------------------------------------------------------
// Scratch (__device__ globals; zero-initialized at module load — PS relies on
// this: slots of masked tiles are never written and read as 0).
// ---------------------------------------------------------------------------
__device__ float g_X [(size_t)BB * SS * DD];          // x (tf32)      32 MB
__device__ float g_Wt[3][(size_t)DD * DD];            // W^T (tf32)    12 MB
__device__ float g_Q [(size_t)BB * SS * DD];          // Q (tf32)      32 MB
__device__ float g_K [(size_t)BB * SS * DD];          // K (tf32)      32 MB
__device__ float g_Vt[(size_t)BB * SS * DD];          // V^T (tf32)    32 MB
__device__ float g_P [(size_t)BB * SS * SS];          // exp-scores     64 MB
__device__ float g_PS[(size_t)BB * SS * 64];          // row partials    2 MB

// ---------------------------------------------------------------------------
// Helpers
// ---------------------------------------------------------------------------
__device__ __forceinline__ uint32_t smem_u32(const void* p) {
    uint32_t a;
    asm("{ .reg .u64 t; cvta.to.shared.u64 t, %1; cvt.u32.u64 %0, t; }"
        : "=r"(a) : "l"(p));
    return a;
}

__device__ __forceinline__ uint32_t tf32r(float f) {
    uint32_t r;
    asm("cvt.rna.tf32.f32 %0, %1;" : "=r"(r) : "f"(f));
    return r;
}

#define LDSM4(r, a)                                                        \
    asm volatile("ldmatrix.sync.aligned.m8n8.x4.shared.b16 "               \
                 "{%0,%1,%2,%3}, [%4];"                                    \
                 : "=r"((r)[0]), "=r"((r)[1]), "=r"((r)[2]), "=r"((r)[3])  \
                 : "r"(a))

#define MMATF32(d, a, b0, b1)                                              \
    asm volatile("mma.sync.aligned.m16n8k8.row.col.f32.tf32.tf32.f32 "     \
                 "{%0,%1,%2,%3},{%4,%5,%6,%7},{%8,%9},{%0,%1,%2,%3};"      \
                 : "+f"((d)[0]), "+f"((d)[1]), "+f"((d)[2]), "+f"((d)[3])  \
                 : "r"((a)[0]), "r"((a)[1]), "r"((a)[2]), "r"((a)[3]),     \
                   "r"(b0), "r"(b1))

#define CPA16(dst, src)                                                    \
    asm volatile("cp.async.cg.shared.global [%0], [%1], 16;"               \
                 :: "r"(dst), "l"(src))
#define CPA_COMMIT()  asm volatile("cp.async.commit_group;" ::: "memory")
#define CPA_WAIT1()   asm volatile("cp.async.wait_group 1;" ::: "memory")

// ===========================================================================
// Shared GEMM body (CTA 128x64, 2-stage cp.async ring, warp tile 32x32).
// 2 stages x 24KB = 48KB/CTA -> 4 CTAs/SM; 64-reg budget (32-bit offsets).
// ===========================================================================
struct GemmCtx {
    uint32_t sbase;
    uint32_t aoffs;
    const float* gA;
    const float* gB;
    int a32, b32;                    // 32-row strides, elements (32-bit)
    uint32_t aSw[2], bSw[2];
    uint32_t hb;
};

__device__ __forceinline__ void gemm_setup(GemmCtx& cx, uint32_t sbase,
                                           const float* A, int lda, int m0,
                                           const float* B, int ldb, int n0,
                                           int tid, int lane, int wid)
{
    cx.sbase = sbase;
    const int wm = (wid & 3) * 32;
    const int wn = (wid >> 2) * 32;

    const int arow = tid >> 3, cu = tid & 7;
    cx.aoffs = ((uint32_t)arow * 128u + (uint32_t)cu * 16u)
               ^ (((uint32_t)(arow & 7)) << 4);
    cx.gA = A + (long long)(m0 + arow) * lda + cu * 4;
    cx.gB = B + (long long)(n0 + arow) * ldb + cu * 4;
    cx.a32 = 32 * lda;
    cx.b32 = 32 * ldb;

    const int fr = lane & 15;
    cx.hb = (uint32_t)(lane >> 4) * 16u;
#pragma unroll
    for (int mf = 0; mf < 2; mf++) {
        int row = wm + 16 * mf + fr;
        cx.aSw[mf] = (uint32_t)row * 128u ^ (((uint32_t)(row & 7)) << 4);
    }
#pragma unroll
    for (int g = 0; g < 2; g++) {
        int row = wn + 16 * g + fr;
        cx.bSw[g] = 16384u + ((uint32_t)row * 128u ^ (((uint32_t)(row & 7)) << 4));
    }
}

__device__ __forceinline__ void gemm_issue(const GemmCtx& cx, int sidx, int k0)
{
    const uint32_t sb_ = cx.sbase + (uint32_t)sidx * STAGE_BYTES;
    CPA16(sb_ + cx.aoffs,          cx.gA + k0);
    CPA16(sb_ + cx.aoffs +  4096u, cx.gA + k0 + cx.a32);
    CPA16(sb_ + cx.aoffs +  8192u, cx.gA + k0 + 2 * cx.a32);
    CPA16(sb_ + cx.aoffs + 12288u, cx.gA + k0 + 3 * cx.a32);
    CPA16(sb_ + 16384u + cx.aoffs,         cx.gB + k0);
    CPA16(sb_ + 16384u + cx.aoffs + 4096u, cx.gB + k0 + cx.b32);
}

__device__ __forceinline__ void gemm_mainloop(const GemmCtx& cx, int KB,
                                              float acc[2][4][4])
{
    // prologue: stage 0
    gemm_issue(cx, 0, 0);
    CPA_COMMIT();

    for (int kb = 0; kb < KB; kb++) {
        // issue the next stage into the buffer computed 2 iterations ago
        // (freed by the end-of-previous-iteration barrier)
        if (kb + 1 < KB) gemm_issue(cx, (kb + 1) & 1, (kb + 1) * TK);
        CPA_COMMIT();                         // empty tail group keeps counts aligned
        CPA_WAIT1();                          // oldest group (stage kb) complete
        __syncthreads();

        const uint32_t buf = cx.sbase + (uint32_t)(kb & 1) * STAGE_BYTES;

#pragma unroll
        for (int kblk = 0; kblk < 4; kblk++) {            // 4 x k8 per k-block
            const uint32_t kc = (uint32_t)(kblk * 32) + cx.hb;
            uint32_t a[2][4], b[2][4];
            LDSM4(a[0], buf + (cx.aSw[0] ^ kc));
            LDSM4(a[1], buf + (cx.aSw[1] ^ kc));
            LDSM4(b[0], buf + (cx.bSw[0] ^ kc));
            LDSM4(b[1], buf + (cx.bSw[1] ^ kc));
#pragma unroll
            for (int mf = 0; mf < 2; mf++)
#pragma unroll
                for (int g = 0; g < 2; g++)
#pragma unroll
                    for (int s = 0; s < 2; s++)
                        MMATF32(acc[mf][2 * g + s], a[mf], b[g][s], b[g][s + 2]);
        }
        __syncthreads();                      // reads done before next overwrite
    }
}

// ---------------------------------------------------------------------------
// Scores kernel, COMPACT triangular grid: grid.x = LIVE_TILES (per batch),
// decoded to (by, bx) with heavy q-tile rows scheduled first.
// P[q,k] = tf32r(exp(scale * QK^T)) for k<=q, 0 for masked elems of live
// tiles. Deterministic per-(row, tile, n-warp) partial sums -> PS.
// ---------------------------------------------------------------------------
__global__ void __launch_bounds__(NTHREADS, 4)
scores_gemm(const float* __restrict__ Q, const float* __restrict__ K,
            float* __restrict__ P, float* __restrict__ PS, float scale)
{
    // triangular decode, heavy rows first
    const int t = LIVE_TILES - 1 - blockIdx.x;           // 0..271
    int by = (int)((sqrtf(4.0f * t + 1.0f) - 1.0f) * 0.5f);
    if ((by + 1) * (by + 2) <= t) by++;
    if (by * (by + 1) > t) by--;
    const int bx = t - by * (by + 1);                    // 0..2(by+1)-1

    const int m0 = by * TM;
    const int n0 = bx * TN;

    extern __shared__ char dsm[];
    const uint32_t sbase = (smem_u32(dsm) + 1023u) & ~1023u;

    const long long z = blockIdx.z;
    const float* A = Q + (long long)z * SS * DD;
    const float* B = K + (long long)z * SS * DD;

    const int tid  = threadIdx.x;
    const int lane = tid & 31;
    const int wid  = tid >> 5;

    GemmCtx cx;
    gemm_setup(cx, sbase, A, DD, m0, B, DD, n0, tid, lane, wid);

    float acc[2][4][4];
#pragma unroll
    for (int mf = 0; mf < 2; mf++)
#pragma unroll
        for (int nf = 0; nf < 4; nf++)
#pragma unroll
            for (int j = 0; j < 4; j++) acc[mf][nf][j] = 0.0f;

    gemm_mainloop(cx, DD / TK, acc);

    // ---- exp epilogue ----
    const int wm = (wid & 3) * 32;
    const int wn = (wid >> 2) * 32;
    const int gq = lane >> 2, tt = lane & 3;
    float* Pz = P + (long long)z * SS * SS;

    float psum[4] = {0.0f, 0.0f, 0.0f, 0.0f};   // [mf*2 + rowhalf]
#pragma unroll
    for (int mf = 0; mf < 2; mf++) {
        const int r0 = m0 + wm + 16 * mf + gq;
#pragma unroll
        for (int nf = 0; nf < 4; nf++) {
            const int col = n0 + wn + 8 * nf + 2 * tt;
            float e00 = (col     <= r0    ) ? __expf(acc[mf][nf][0] * scale) : 0.0f;
            float e01 = (col + 1 <= r0    ) ? __expf(acc[mf][nf][1] * scale) : 0.0f;
            float e10 = (col     <= r0 + 8) ? __expf(acc[mf][nf][2] * scale) : 0.0f;
            float e11 = (col + 1 <= r0 + 8) ? __expf(acc[mf][nf][3] * scale) : 0.0f;
            e00 = __uint_as_float(tf32r(e00));
            e01 = __uint_as_float(tf32r(e01));
            e10 = __uint_as_float(tf32r(e10));
            e11 = __uint_as_float(tf32r(e11));
            float2 o0, o1;
            o0.x = e00; o0.y = e01;
            o1.x = e10; o1.y = e11;
            *reinterpret_cast<float2*>(Pz + (long long)r0 * SS + col)       = o0;
            *reinterpret_cast<float2*>(Pz + (long long)(r0 + 8) * SS + col) = o1;
            psum[mf * 2]     += e00 + e01;
            psum[mf * 2 + 1] += e10 + e11;
        }
    }
#pragma unroll
    for (int off = 1; off <= 2; off <<= 1)
#pragma unroll
        for (int i = 0; i < 4; i++)
            psum[i] += __shfl_xor_sync(0xFFFFFFFFu, psum[i], off);

    if (tt == 0) {
        const int slot = bx * 2 + (wid >> 2);
        const size_t rb = (size_t)z * SS;
        const int rbase = m0 + wm + gq;
        PS[(rb + rbase)      * 64 + slot] = psum[0];
        PS[(rb + rbase + 8)  * 64 + slot] = psum[1];
        PS[(rb + rbase + 16) * 64 + slot] = psum[2];
        PS[(rb + rbase + 24) * 64 + slot] = psum[3];
    }
}

// ---------------------------------------------------------------------------
// P@V kernel: out[q,d] = (1/rowsum(q)) * sum_k P[q,k]*Vt[d,k]; per-q K limit.
// Row-sum inverses from PS in the prologue, slot-split across the 4 tt lanes
// (16 loads/thread instead of 64) + butterfly reduce. Deterministic.
// ---------------------------------------------------------------------------
__global__ void __launch_bounds__(NTHREADS, 4)
pv_gemm(const float* __restrict__ P, const float* __restrict__ Vt,
        const float* __restrict__ PS, float* __restrict__ Out)
{
    const int by = gridDim.y - 1 - blockIdx.y;     // heavy rows first
    const int m0 = by * TM;
    const int n0 = blockIdx.x * TN;

    extern __shared__ char dsm[];
    const uint32_t sbase = (smem_u32(dsm) + 1023u) & ~1023u;

    const long long z = blockIdx.z;
    const float* A = P  + (long long)z * SS * SS;
    const float* B = Vt + (long long)z * SS * DD;

    const int KB = ((by + 1) * TM) / TK;

    const int tid  = threadIdx.x;
    const int lane = tid & 31;
    const int wid  = tid >> 5;

    // ---- per-thread row-sum inverses (slot-split over tt, butterfly) ----
    const int wm = (wid & 3) * 32;
    const int gq = lane >> 2, tt = lane & 3;
    float inv[4];
    {
        const size_t rb = (size_t)z * SS;
        const int rbase = m0 + wm + gq;
#pragma unroll
        for (int r = 0; r < 4; r++) {
            const float4* ps = reinterpret_cast<const float4*>(
                PS + (rb + rbase + 8 * r) * 64) + tt * 4;
            float s = 0.0f;
#pragma unroll
            for (int j = 0; j < 4; j++) {
                float4 v = ps[j];
                s += (v.x + v.y) + (v.z + v.w);
            }
            s += __shfl_xor_sync(0xFFFFFFFFu, s, 1);
            s += __shfl_xor_sync(0xFFFFFFFFu, s, 2);
            inv[r] = 1.0f / s;
        }
    }

    GemmCtx cx;
    gemm_setup(cx, sbase, A, SS, m0, B, SS, n0, tid, lane, wid);

    float acc[2][4][4];
#pragma unroll
    for (int mf = 0; mf < 2; mf++)
#pragma unroll
        for (int nf = 0; nf < 4; nf++)
#pragma unroll
            for (int j = 0; j < 4; j++) acc[mf][nf][j] = 0.0f;

    gemm_mainloop(cx, KB, acc);

    // epilogue: scale by 1/rowsum
    const int wn = (wid >> 2) * 32;
    float* C = Out + (long long)z * SS * DD;
#pragma unroll
    for (int mf = 0; mf < 2; mf++) {
        const int r0 = m0 + wm + 16 * mf + gq;
        const float inv0 = inv[mf * 2];
        const float inv1 = inv[mf * 2 + 1];
#pragma unroll
        for (int nf = 0; nf < 4; nf++) {
            const int col = n0 + wn + 8 * nf + 2 * tt;
            float2 o0, o1;
            o0.x = acc[mf][nf][0] * inv0;
            o0.y = acc[mf][nf][1] * inv0;
            o1.x = acc[mf][nf][2] * inv1;
            o1.y = acc[mf][nf][3] * inv1;
            *reinterpret_cast<float2*>(C + (long long)r0 * DD + col)       = o0;
            *reinterpret_cast<float2*>(C + (long long)(r0 + 8) * DD + col) = o1;
        }
    }
}

// ---------------------------------------------------------------------------
// Fused QKV kernel: blockIdx.z in 0..2 selects {Wq,Wk,Wv}.
//   z=0/1: Q/K written tf32-rounded, row-major.
//   z=2  : V written directly transposed (per-batch [DD][SS]) + tf32-rounded.
// ---------------------------------------------------------------------------
__global__ void __launch_bounds__(NTHREADS, 4)
qkv_gemm(const float* __restrict__ X, const float* __restrict__ Wt,
         float* __restrict__ Qo, float* __restrict__ Ko, float* __restrict__ VtO)
{
    const int m0 = blockIdx.y * TM;
    const int n0 = blockIdx.x * TN;
    const int z  = blockIdx.z;

    extern __shared__ char dsm[];
    const uint32_t sbase = (smem_u32(dsm) + 1023u) & ~1023u;

    const float* B = Wt + (size_t)z * DD * DD;

    const int tid  = threadIdx.x;
    const int lane = tid & 31;
    const int wid  = tid >> 5;

    GemmCtx cx;
    gemm_setup(cx, sbase, X, DD, m0, B, DD, n0, tid, lane, wid);

    float acc[2][4][4];
#pragma unroll
    for (int mf = 0; mf < 2; mf++)
#pragma unroll
        for (int nf = 0; nf < 4; nf++)
#pragma unroll
            for (int j = 0; j < 4; j++) acc[mf][nf][j] = 0.0f;

    gemm_mainloop(cx, DD / TK, acc);

    const int wm = (wid & 3) * 32;
    const int wn = (wid >> 2) * 32;
    const int gq = lane >> 2, t = lane & 3;

    if (z < 2) {
        float* C = (z == 0) ? Qo : Ko;
#pragma unroll
        for (int mf = 0; mf < 2; mf++) {
#pragma unroll
            for (int nf = 0; nf < 4; nf++) {
                const int r0  = m0 + wm + 16 * mf + gq;
                const int col = n0 + wn + 8 * nf + 2 * t;
                float2 o0, o1;
                o0.x = __uint_as_float(tf32r(acc[mf][nf][0]));
                o0.y = __uint_as_float(tf32r(acc[mf][nf][1]));
                o1.x = __uint_as_float(tf32r(acc[mf][nf][2]));
                o1.y = __uint_as_float(tf32r(acc[mf][nf][3]));
                *reinterpret_cast<float2*>(C + (long long)r0 * DD + col)       = o0;
                *reinterpret_cast<float2*>(C + (long long)(r0 + 8) * DD + col) = o1;
            }
        }
    } else {
        // ---- transposed V epilogue ----
        __syncthreads();                       // pipeline smem now free
        float* ts = reinterpret_cast<float*>(dsm +
                        (size_t)(sbase - smem_u32(dsm)));   // aligned base
#pragma unroll
        for (int mf = 0; mf < 2; mf++) {
#pragma unroll
            for (int nf = 0; nf < 4; nf++) {
                const int m_ = wm + 16 * mf + gq;
                const int n_ = wn + 8 * nf + 2 * t;
                ts[n_ * 132 + m_]             = acc[mf][nf][0];
                ts[(n_ + 1) * 132 + m_]       = acc[mf][nf][1];
                ts[n_ * 132 + m_ + 8]         = acc[mf][nf][2];
                ts[(n_ + 1) * 132 + m_ + 8]   = acc[mf][nf][3];
            }
        }
        __syncthreads();
        const int vr = tid >> 2;
        const int vc = tid & 3;
        const int b  = m0 >> 11;               // batch (S = 2048)
        const int s0 = m0 & (SS - 1);
        float* dst = VtO + (size_t)b * SS * DD
                   + (size_t)(n0 + vr) * SS + s0 + vc * 32;
#pragma unroll
        for (int i = 0; i < 8; i++) {
            float4 v = *reinterpret_cast<const float4*>(
                ts + vr * 132 + vc * 32 + i * 4);
            v.x = __uint_as_float(tf32r(v.x));
            v.y = __uint_as_float(tf32r(v.y));
            v.z = __uint_as_float(tf32r(v.z));
            v.w = __uint_as_float(tf32r(v.w));
            *reinterpret_cast<float4*>(dst + i * 4) = v;
        }
    }
}

// ---------------------------------------------------------------------------
// Prep kernel (merged): blocks [0, XN4B) convert x -> tf32; remaining blocks
// transpose Wq/Wk/Wv -> Wt (K-major, tf32).
// ---------------------------------------------------------------------------
#define XN4   (BB * SS * DD / 4)
#define XN4B  ((XN4 + 255) / 256)              // 8192 blocks
#define WTB   (3 * (DD / 32) * (DD / 32))      // 3072 blocks

__global__ void __launch_bounds__(256)
prep_kernel(const float* __restrict__ x, float* __restrict__ X,
            const float* __restrict__ Wq, const float* __restrict__ Wk,
            const float* __restrict__ Wv, float* __restrict__ WtBase)
{
    __shared__ float t[32][33];
    const int b = blockIdx.x;
    const int tid = threadIdx.x;

    if (b < XN4B) {
        const int i = b * 256 + tid;
        if (i >= XN4) return;
        float4 v = reinterpret_cast<const float4*>(x)[i];
        v.x = __uint_as_float(tf32r(v.x));
        v.y = __uint_as_float(tf32r(v.y));
        v.z = __uint_as_float(tf32r(v.z));
        v.w = __uint_as_float(tf32r(v.w));
        reinterpret_cast<float4*>(X)[i] = v;
    } else {
        const int idx = b - XN4B;
        const int z   = idx >> 10;                  // /1024
        const int rem = idx & 1023;
        const int bx  = rem & 31;
        const int byy = rem >> 5;
        const float* in = (z == 0) ? Wq : (z == 1) ? Wk : Wv;
        float* out = WtBase + (size_t)z * DD * DD;
        const int c0 = bx * 32, r0 = byy * 32;
        const int tx = tid & 31, ty = tid >> 5;     // (32, 8)
#pragma unroll
        for (int j = ty; j < 32; j += 8)
            t[j][tx] = in[(long long)(r0 + j) * DD + c0 + tx];
        __syncthreads();
#pragma unroll
        for (int j = ty; j < 32; j += 8)
            out[(long long)(c0 + j) * DD + r0 + tx] =
                __uint_as_float(tf32r(t[tx][j]));
    }
}

// ---------------------------------------------------------------------------
// Launch sequence (graph-capturable: kernel launches only).
// prep(0), QKV+Vt(1), scores+exp compact(2), P@V+rowinv(3) — 4 nodes.
// ---------------------------------------------------------------------------
extern "C" void kernel_launch(void* const* d_in, const int* in_sizes, int n_in,
                              void* d_out, int out_size)
{
    const float* x  = (const float*)d_in[0];
    const float* Wq = (const float*)d_in[1];
    const float* Wk = (const float*)d_in[2];
    const float* Wv = (const float*)d_in[3];
    float* out = (float*)d_out;

    float *X, *Wt, *Q, *K, *Vt, *P, *PS;
    cudaGetSymbolAddress((void**)&X,  g_X);
    cudaGetSymbolAddress((void**)&Wt, g_Wt);
    cudaGetSymbolAddress((void**)&Q,  g_Q);
    cudaGetSymbolAddress((void**)&K,  g_K);
    cudaGetSymbolAddress((void**)&Vt, g_Vt);
    cudaGetSymbolAddress((void**)&P,  g_P);
    cudaGetSymbolAddress((void**)&PS, g_PS);

    cudaFuncSetAttribute(qkv_gemm,
                         cudaFuncAttributeMaxDynamicSharedMemorySize, DSM_BYTES);
    cudaFuncSetAttribute(scores_gemm,
                         cudaFuncAttributeMaxDynamicSharedMemorySize, DSM_BYTES);
    cudaFuncSetAttribute(pv_gemm,
                         cudaFuncAttributeMaxDynamicSharedMemorySize, DSM_BYTES);

    const float scale = 0.03125f;     // 1024^-0.5

    // idx 0) prep: x -> tf32, W -> W^T (merged)
    prep_kernel<<<XN4B + WTB, 256>>>(x, X, Wq, Wk, Wv, Wt);

    // idx 1) Fused QKV projection; V emitted transposed (per-batch [DD][SS])
    dim3 gq(DD / TN, (BB * SS) / TM, 3);
    qkv_gemm<<<gq, NTHREADS, DSM_BYTES>>>(X, Wt, Q, K, Vt);

    // idx 2) P = exp(scale * Q K^T), masked; partial row sums to PS
    //         compact triangular grid: only live tiles launched
    dim3 gs(LIVE_TILES, 1, BB);
    scores_gemm<<<gs, NTHREADS, DSM_BYTES>>>(Q, K, P, PS, scale);

    // idx 3) out = (1/rowsum) * (P @ V); rowsum inverses from PS in-prologue
    dim3 gp(DD / TN, SS / TM, BB);
    pv_gemm<<<gp, NTHREADS, DSM_BYTES>>>(P, Vt, PS, out);
}

// round 16
// speedup vs baseline: 1.2804x; 1.2804x over previous
#include <cuda_runtime.h>
#include <cstdint>
#include <math.h>

#define BB 4
#define SS 2048
#define DD 1024

#define TM 128
#define TN 64
#define TK 32
#define NTHREADS 256
#define STAGES 3
#define STAGE_BYTES 24576            // A fp32 16K | B fp32 8K
#define DSM_BYTES (STAGES * STAGE_BYTES + 1024)

// live score tiles per batch: sum_{by=0}^{15} 2(by+1) = 272
#define LIVE_TILES 272

// ---------------------------------------------------------------------------
// Scratch (__device__ globals; zero-initialized at module load — PS relies on
// this: slots of masked tiles are never written and read as 0).
// ---------------------------------------------------------------------------
__device__ float g_X [(size_t)BB * SS * DD];          // x (tf32)      32 MB
__device__ float g_Wt[3][(size_t)DD * DD];            // W^T (tf32)    12 MB
__device__ float g_Q [(size_t)BB * SS * DD];          // Q (tf32)      32 MB
__device__ float g_K [(size_t)BB * SS * DD];          // K (tf32)      32 MB
__device__ float g_Vt[(size_t)BB * SS * DD];          // V^T (tf32)    32 MB
__device__ float g_P [(size_t)BB * SS * SS];          // exp-scores     64 MB
__device__ float g_PS[(size_t)BB * SS * 64];          // row partials    2 MB

// ---------------------------------------------------------------------------
// Helpers
// ---------------------------------------------------------------------------
__device__ __forceinline__ uint32_t smem_u32(const void* p) {
    uint32_t a;
    asm("{ .reg .u64 t; cvta.to.shared.u64 t, %1; cvt.u32.u64 %0, t; }"
        : "=r"(a) : "l"(p));
    return a;
}

__device__ __forceinline__ uint32_t tf32r(float f) {
    uint32_t r;
    asm("cvt.rna.tf32.f32 %0, %1;" : "=r"(r) : "f"(f));
    return r;
}

#define LDSM4(r, a)                                                        \
    asm volatile("ldmatrix.sync.aligned.m8n8.x4.shared.b16 "               \
                 "{%0,%1,%2,%3}, [%4];"                                    \
                 : "=r"((r)[0]), "=r"((r)[1]), "=r"((r)[2]), "=r"((r)[3])  \
                 : "r"(a))

#define MMATF32(d, a, b0, b1)                                              \
    asm volatile("mma.sync.aligned.m16n8k8.row.col.f32.tf32.tf32.f32 "     \
                 "{%0,%1,%2,%3},{%4,%5,%6,%7},{%8,%9},{%0,%1,%2,%3};"      \
                 : "+f"((d)[0]), "+f"((d)[1]), "+f"((d)[2]), "+f"((d)[3])  \
                 : "r"((a)[0]), "r"((a)[1]), "r"((a)[2]), "r"((a)[3]),     \
                   "r"(b0), "r"(b1))

#define CPA16(dst, src)                                                    \
    asm volatile("cp.async.cg.shared.global [%0], [%1], 16;"               \
                 :: "r"(dst), "l"(src))
#define CPA_COMMIT()  asm volatile("cp.async.commit_group;" ::: "memory")
#define CPA_WAIT1()   asm volatile("cp.async.wait_group 1;" ::: "memory")

// ===========================================================================
// Shared GEMM body (CTA 128x64, 3-stage cp.async, warp tile 32x32).
// R14-proven geometry: 3 stages, 3 CTAs/SM, single-buffered fragments,
// next-stage burst issued after kblk0's critical path.
// ===========================================================================
struct GemmCtx {
    uint32_t sbase;
    uint32_t aoffs;
    const float* gA;
    const float* gB;
    int a32, b32;                    // 32-row strides, elements (32-bit)
    uint32_t aSw[2], bSw[2];
    uint32_t hb;
};

__device__ __forceinline__ void gemm_setup(GemmCtx& cx, uint32_t sbase,
                                           const float* A, int lda, int m0,
                                           const float* B, int ldb, int n0,
                                           int tid, int lane, int wid)
{
    cx.sbase = sbase;
    const int wm = (wid & 3) * 32;
    const int wn = (wid >> 2) * 32;

    const int arow = tid >> 3, cu = tid & 7;
    cx.aoffs = ((uint32_t)arow * 128u + (uint32_t)cu * 16u)
               ^ (((uint32_t)(arow & 7)) << 4);
    cx.gA = A + (long long)(m0 + arow) * lda + cu * 4;
    cx.gB = B + (long long)(n0 + arow) * ldb + cu * 4;
    cx.a32 = 32 * lda;
    cx.b32 = 32 * ldb;

    const int fr = lane & 15;
    cx.hb = (uint32_t)(lane >> 4) * 16u;
#pragma unroll
    for (int mf = 0; mf < 2; mf++) {
        int row = wm + 16 * mf + fr;
        cx.aSw[mf] = (uint32_t)row * 128u ^ (((uint32_t)(row & 7)) << 4);
    }
#pragma unroll
    for (int g = 0; g < 2; g++) {
        int row = wn + 16 * g + fr;
        cx.bSw[g] = 16384u + ((uint32_t)row * 128u ^ (((uint32_t)(row & 7)) << 4));
    }
}

__device__ __forceinline__ void gemm_issue(const GemmCtx& cx, int sidx, int k0)
{
    const uint32_t sb_ = cx.sbase + (uint32_t)sidx * STAGE_BYTES;
    CPA16(sb_ + cx.aoffs,          cx.gA + k0);
    CPA16(sb_ + cx.aoffs +  4096u, cx.gA + k0 + cx.a32);
    CPA16(sb_ + cx.aoffs +  8192u, cx.gA + k0 + 2 * cx.a32);
    CPA16(sb_ + cx.aoffs + 12288u, cx.gA + k0 + 3 * cx.a32);
    CPA16(sb_ + 16384u + cx.aoffs,         cx.gB + k0);
    CPA16(sb_ + 16384u + cx.aoffs + 4096u, cx.gB + k0 + cx.b32);
}

__device__ __forceinline__ void gemm_mainloop(const GemmCtx& cx, int KB,
                                              float acc[2][4][4])
{
#pragma unroll
    for (int s = 0; s < STAGES - 1; s++) {
        if (s < KB) gemm_issue(cx, s, s * TK);
        CPA_COMMIT();
    }

    int sidx_c = 0;
    int sidx_w = STAGES - 1;
    for (int kb = 0; kb < KB; kb++) {
        CPA_WAIT1();
        __syncthreads();

        const uint32_t buf = cx.sbase + (uint32_t)sidx_c * STAGE_BYTES;
        if (++sidx_c == STAGES) sidx_c = 0;

#pragma unroll
        for (int kblk = 0; kblk < 4; kblk++) {            // 4 x k8 per k-block
            const uint32_t kc = (uint32_t)(kblk * 32) + cx.hb;
            uint32_t a[2][4], b[2][4];
            LDSM4(a[0], buf + (cx.aSw[0] ^ kc));
            LDSM4(a[1], buf + (cx.aSw[1] ^ kc));
            LDSM4(b[0], buf + (cx.bSw[0] ^ kc));
            LDSM4(b[1], buf + (cx.bSw[1] ^ kc));
#pragma unroll
            for (int mf = 0; mf < 2; mf++)
#pragma unroll
                for (int g = 0; g < 2; g++)
#pragma unroll
                    for (int s = 0; s < 2; s++)
                        MMATF32(acc[mf][2 * g + s], a[mf], b[g][s], b[g][s + 2]);

            if (kblk == 0) {
                if (kb + STAGES - 1 < KB)
                    gemm_issue(cx, sidx_w, (kb + STAGES - 1) * TK);
                CPA_COMMIT();
                if (++sidx_w == STAGES) sidx_w = 0;
            }
        }
    }
}

// ---------------------------------------------------------------------------
// Scores kernel, COMPACT triangular grid: grid.x = LIVE_TILES (per batch),
// decoded to (by, bx) with heavy q-tile rows scheduled first.
// P[q,k] = tf32r(exp(scale * QK^T)) for k<=q, 0 for masked elems of live
// tiles. Deterministic per-(row, tile, n-warp) partial sums -> PS.
// ---------------------------------------------------------------------------
__global__ void __launch_bounds__(NTHREADS, 3)
scores_gemm(const float* __restrict__ Q, const float* __restrict__ K,
            float* __restrict__ P, float* __restrict__ PS, float scale)
{
    // triangular decode, heavy rows first
    const int t = LIVE_TILES - 1 - blockIdx.x;           // 0..271
    int by = (int)((sqrtf(4.0f * t + 1.0f) - 1.0f) * 0.5f);
    if ((by + 1) * (by + 2) <= t) by++;
    if (by * (by + 1) > t) by--;
    const int bx = t - by * (by + 1);                    // 0..2(by+1)-1

    const int m0 = by * TM;
    const int n0 = bx * TN;

    extern __shared__ char dsm[];
    const uint32_t sbase = (smem_u32(dsm) + 1023u) & ~1023u;

    const long long z = blockIdx.z;
    const float* A = Q + (long long)z * SS * DD;
    const float* B = K + (long long)z * SS * DD;

    const int tid  = threadIdx.x;
    const int lane = tid & 31;
    const int wid  = tid >> 5;

    GemmCtx cx;
    gemm_setup(cx, sbase, A, DD, m0, B, DD, n0, tid, lane, wid);

    float acc[2][4][4];
#pragma unroll
    for (int mf = 0; mf < 2; mf++)
#pragma unroll
        for (int nf = 0; nf < 4; nf++)
#pragma unroll
            for (int j = 0; j < 4; j++) acc[mf][nf][j] = 0.0f;

    gemm_mainloop(cx, DD / TK, acc);

    // ---- exp epilogue ----
    const int wm = (wid & 3) * 32;
    const int wn = (wid >> 2) * 32;
    const int gq = lane >> 2, tt = lane & 3;
    float* Pz = P + (long long)z * SS * SS;

    float psum[4] = {0.0f, 0.0f, 0.0f, 0.0f};   // [mf*2 + rowhalf]
#pragma unroll
    for (int mf = 0; mf < 2; mf++) {
        const int r0 = m0 + wm + 16 * mf + gq;
#pragma unroll
        for (int nf = 0; nf < 4; nf++) {
            const int col = n0 + wn + 8 * nf + 2 * tt;
            float e00 = (col     <= r0    ) ? __expf(acc[mf][nf][0] * scale) : 0.0f;
            float e01 = (col + 1 <= r0    ) ? __expf(acc[mf][nf][1] * scale) : 0.0f;
            float e10 = (col     <= r0 + 8) ? __expf(acc[mf][nf][2] * scale) : 0.0f;
            float e11 = (col + 1 <= r0 + 8) ? __expf(acc[mf][nf][3] * scale) : 0.0f;
            e00 = __uint_as_float(tf32r(e00));
            e01 = __uint_as_float(tf32r(e01));
            e10 = __uint_as_float(tf32r(e10));
            e11 = __uint_as_float(tf32r(e11));
            float2 o0, o1;
            o0.x = e00; o0.y = e01;
            o1.x = e10; o1.y = e11;
            *reinterpret_cast<float2*>(Pz + (long long)r0 * SS + col)       = o0;
            *reinterpret_cast<float2*>(Pz + (long long)(r0 + 8) * SS + col) = o1;
            psum[mf * 2]     += e00 + e01;
            psum[mf * 2 + 1] += e10 + e11;
        }
    }
#pragma unroll
    for (int off = 1; off <= 2; off <<= 1)
#pragma unroll
        for (int i = 0; i < 4; i++)
            psum[i] += __shfl_xor_sync(0xFFFFFFFFu, psum[i], off);

    if (tt == 0) {
        const int slot = bx * 2 + (wid >> 2);
        const size_t rb = (size_t)z * SS;
        const int rbase = m0 + wm + gq;
        PS[(rb + rbase)      * 64 + slot] = psum[0];
        PS[(rb + rbase + 8)  * 64 + slot] = psum[1];
        PS[(rb + rbase + 16) * 64 + slot] = psum[2];
        PS[(rb + rbase + 24) * 64 + slot] = psum[3];
    }
}

// ---------------------------------------------------------------------------
// P@V kernel: out[q,d] = (1/rowsum(q)) * sum_k P[q,k]*Vt[d,k]; per-q K limit.
// Row-sum inverses from PS in the prologue, slot-split across the 4 tt lanes
// (16 loads/thread instead of 64) + butterfly reduce. Deterministic.
// ---------------------------------------------------------------------------
__global__ void __launch_bounds__(NTHREADS, 3)
pv_gemm(const float* __restrict__ P, const float* __restrict__ Vt,
        const float* __restrict__ PS, float* __restrict__ Out)
{
    const int by = gridDim.y - 1 - blockIdx.y;     // heavy rows first
    const int m0 = by * TM;
    const int n0 = blockIdx.x * TN;

    extern __shared__ char dsm[];
    const uint32_t sbase = (smem_u32(dsm) + 1023u) & ~1023u;

    const long long z = blockIdx.z;
    const float* A = P  + (long long)z * SS * SS;
    const float* B = Vt + (long long)z * SS * DD;

    const int KB = ((by + 1) * TM) / TK;

    const int tid  = threadIdx.x;
    const int lane = tid & 31;
    const int wid  = tid >> 5;

    // ---- per-thread row-sum inverses (slot-split over tt, butterfly) ----
    const int wm = (wid & 3) * 32;
    const int gq = lane >> 2, tt = lane & 3;
    float inv[4];
    {
        const size_t rb = (size_t)z * SS;
        const int rbase = m0 + wm + gq;
#pragma unroll
        for (int r = 0; r < 4; r++) {
            const float4* ps = reinterpret_cast<const float4*>(
                PS + (rb + rbase + 8 * r) * 64) + tt * 4;
            float s = 0.0f;
#pragma unroll
            for (int j = 0; j < 4; j++) {
                float4 v = ps[j];
                s += (v.x + v.y) + (v.z + v.w);
            }
            s += __shfl_xor_sync(0xFFFFFFFFu, s, 1);
            s += __shfl_xor_sync(0xFFFFFFFFu, s, 2);
            inv[r] = 1.0f / s;
        }
    }

    GemmCtx cx;
    gemm_setup(cx, sbase, A, SS, m0, B, SS, n0, tid, lane, wid);

    float acc[2][4][4];
#pragma unroll
    for (int mf = 0; mf < 2; mf++)
#pragma unroll
        for (int nf = 0; nf < 4; nf++)
#pragma unroll
            for (int j = 0; j < 4; j++) acc[mf][nf][j] = 0.0f;

    gemm_mainloop(cx, KB, acc);

    // epilogue: scale by 1/rowsum
    const int wn = (wid >> 2) * 32;
    float* C = Out + (long long)z * SS * DD;
#pragma unroll
    for (int mf = 0; mf < 2; mf++) {
        const int r0 = m0 + wm + 16 * mf + gq;
        const float inv0 = inv[mf * 2];
        const float inv1 = inv[mf * 2 + 1];
#pragma unroll
        for (int nf = 0; nf < 4; nf++) {
            const int col = n0 + wn + 8 * nf + 2 * tt;
            float2 o0, o1;
            o0.x = acc[mf][nf][0] * inv0;
            o0.y = acc[mf][nf][1] * inv0;
            o1.x = acc[mf][nf][2] * inv1;
            o1.y = acc[mf][nf][3] * inv1;
            *reinterpret_cast<float2*>(C + (long long)r0 * DD + col)       = o0;
            *reinterpret_cast<float2*>(C + (long long)(r0 + 8) * DD + col) = o1;
        }
    }
}

// ---------------------------------------------------------------------------
// Fused QKV kernel: blockIdx.z in 0..2 selects {Wq,Wk,Wv}.
//   z=0/1: Q/K written tf32-rounded, row-major.
//   z=2  : V written directly transposed (per-batch [DD][SS]) + tf32-rounded.
// ---------------------------------------------------------------------------
__global__ void __launch_bounds__(NTHREADS, 3)
qkv_gemm(const float* __restrict__ X, const float* __restrict__ Wt,
         float* __restrict__ Qo, float* __restrict__ Ko, float* __restrict__ VtO)
{
    const int m0 = blockIdx.y * TM;
    const int n0 = blockIdx.x * TN;
    const int z  = blockIdx.z;

    extern __shared__ char dsm[];
    const uint32_t sbase = (smem_u32(dsm) + 1023u) & ~1023u;

    const float* B = Wt + (size_t)z * DD * DD;

    const int tid  = threadIdx.x;
    const int lane = tid & 31;
    const int wid  = tid >> 5;

    GemmCtx cx;
    gemm_setup(cx, sbase, X, DD, m0, B, DD, n0, tid, lane, wid);

    float acc[2][4][4];
#pragma unroll
    for (int mf = 0; mf < 2; mf++)
#pragma unroll
        for (int nf = 0; nf < 4; nf++)
#pragma unroll
            for (int j = 0; j < 4; j++) acc[mf][nf][j] = 0.0f;

    gemm_mainloop(cx, DD / TK, acc);

    const int wm = (wid & 3) * 32;
    const int wn = (wid >> 2) * 32;
    const int gq = lane >> 2, t = lane & 3;

    if (z < 2) {
        float* C = (z == 0) ? Qo : Ko;
#pragma unroll
        for (int mf = 0; mf < 2; mf++) {
#pragma unroll
            for (int nf = 0; nf < 4; nf++) {
                const int r0  = m0 + wm + 16 * mf + gq;
                const int col = n0 + wn + 8 * nf + 2 * t;
                float2 o0, o1;
                o0.x = __uint_as_float(tf32r(acc[mf][nf][0]));
                o0.y = __uint_as_float(tf32r(acc[mf][nf][1]));
                o1.x = __uint_as_float(tf32r(acc[mf][nf][2]));
                o1.y = __uint_as_float(tf32r(acc[mf][nf][3]));
                *reinterpret_cast<float2*>(C + (long long)r0 * DD + col)       = o0;
                *reinterpret_cast<float2*>(C + (long long)(r0 + 8) * DD + col) = o1;
            }
        }
    } else {
        // ---- transposed V epilogue ----
        __syncthreads();                       // pipeline smem now free
        float* ts = reinterpret_cast<float*>(dsm +
                        (size_t)(sbase - smem_u32(dsm)));   // aligned base
#pragma unroll
        for (int mf = 0; mf < 2; mf++) {
#pragma unroll
            for (int nf = 0; nf < 4; nf++) {
                const int m_ = wm + 16 * mf + gq;
                const int n_ = wn + 8 * nf + 2 * t;
                ts[n_ * 132 + m_]             = acc[mf][nf][0];
                ts[(n_ + 1) * 132 + m_]       = acc[mf][nf][1];
                ts[n_ * 132 + m_ + 8]         = acc[mf][nf][2];
                ts[(n_ + 1) * 132 + m_ + 8]   = acc[mf][nf][3];
            }
        }
        __syncthreads();
        const int vr = tid >> 2;
        const int vc = tid & 3;
        const int b  = m0 >> 11;               // batch (S = 2048)
        const int s0 = m0 & (SS - 1);
        float* dst = VtO + (size_t)b * SS * DD
                   + (size_t)(n0 + vr) * SS + s0 + vc * 32;
#pragma unroll
        for (int i = 0; i < 8; i++) {
            float4 v = *reinterpret_cast<const float4*>(
                ts + vr * 132 + vc * 32 + i * 4);
            v.x = __uint_as_float(tf32r(v.x));
            v.y = __uint_as_float(tf32r(v.y));
            v.z = __uint_as_float(tf32r(v.z));
            v.w = __uint_as_float(tf32r(v.w));
            *reinterpret_cast<float4*>(dst + i * 4) = v;
        }
    }
}

// ---------------------------------------------------------------------------
// Prep kernel (merged): blocks [0, XN4B) convert x -> tf32; remaining blocks
// transpose Wq/Wk/Wv -> Wt (K-major, tf32).
// ---------------------------------------------------------------------------
#define XN4   (BB * SS * DD / 4)
#define XN4B  ((XN4 + 255) / 256)              // 8192 blocks
#define WTB   (3 * (DD / 32) * (DD / 32))      // 3072 blocks

__global__ void __launch_bounds__(256)
prep_kernel(const float* __restrict__ x, float* __restrict__ X,
            const float* __restrict__ Wq, const float* __restrict__ Wk,
            const float* __restrict__ Wv, float* __restrict__ WtBase)
{
    __shared__ float t[32][33];
    const int b = blockIdx.x;
    const int tid = threadIdx.x;

    if (b < XN4B) {
        const int i = b * 256 + tid;
        if (i >= XN4) return;
        float4 v = reinterpret_cast<const float4*>(x)[i];
        v.x = __uint_as_float(tf32r(v.x));
        v.y = __uint_as_float(tf32r(v.y));
        v.z = __uint_as_float(tf32r(v.z));
        v.w = __uint_as_float(tf32r(v.w));
        reinterpret_cast<float4*>(X)[i] = v;
    } else {
        const int idx = b - XN4B;
        const int z   = idx >> 10;                  // /1024
        const int rem = idx & 1023;
        const int bx  = rem & 31;
        const int byy = rem >> 5;
        const float* in = (z == 0) ? Wq : (z == 1) ? Wk : Wv;
        float* out = WtBase + (size_t)z * DD * DD;
        const int c0 = bx * 32, r0 = byy * 32;
        const int tx = tid & 31, ty = tid >> 5;     // (32, 8)
#pragma unroll
        for (int j = ty; j < 32; j += 8)
            t[j][tx] = in[(long long)(r0 + j) * DD + c0 + tx];
        __syncthreads();
#pragma unroll
        for (int j = ty; j < 32; j += 8)
            out[(long long)(c0 + j) * DD + r0 + tx] =
                __uint_as_float(tf32r(t[tx][j]));
    }
}

// ---------------------------------------------------------------------------
// Launch sequence (graph-capturable: kernel launches only).
// prep(0), QKV+Vt(1), scores+exp compact(2), P@V+rowinv(3) — 4 nodes.
// ---------------------------------------------------------------------------
extern "C" void kernel_launch(void* const* d_in, const int* in_sizes, int n_in,
                              void* d_out, int out_size)
{
    const float* x  = (const float*)d_in[0];
    const float* Wq = (const float*)d_in[1];
    const float* Wk = (const float*)d_in[2];
    const float* Wv = (const float*)d_in[3];
    float* out = (float*)d_out;

    float *X, *Wt, *Q, *K, *Vt, *P, *PS;
    cudaGetSymbolAddress((void**)&X,  g_X);
    cudaGetSymbolAddress((void**)&Wt, g_Wt);
    cudaGetSymbolAddress((void**)&Q,  g_Q);
    cudaGetSymbolAddress((void**)&K,  g_K);
    cudaGetSymbolAddress((void**)&Vt, g_Vt);
    cudaGetSymbolAddress((void**)&P,  g_P);
    cudaGetSymbolAddress((void**)&PS, g_PS);

    cudaFuncSetAttribute(qkv_gemm,
                         cudaFuncAttributeMaxDynamicSharedMemorySize, DSM_BYTES);
    cudaFuncSetAttribute(scores_gemm,
                         cudaFuncAttributeMaxDynamicSharedMemorySize, DSM_BYTES);
    cudaFuncSetAttribute(pv_gemm,
                         cudaFuncAttributeMaxDynamicSharedMemorySize, DSM_BYTES);

    const float scale = 0.03125f;     // 1024^-0.5

    // idx 0) prep: x -> tf32, W -> W^T (merged)
    prep_kernel<<<XN4B + WTB, 256>>>(x, X, Wq, Wk, Wv, Wt);

    // idx 1) Fused QKV projection; V emitted transposed (per-batch [DD][SS])
    dim3 gq(DD / TN, (BB * SS) / TM, 3);
    qkv_gemm<<<gq, NTHREADS, DSM_BYTES>>>(X, Wt, Q, K, Vt);

    // idx 2) P = exp(scale * Q K^T), masked; partial row sums to PS
    //         compact triangular grid: only live tiles launched
    dim3 gs(LIVE_TILES, 1, BB);
    scores_gemm<<<gs, NTHREADS, DSM_BYTES>>>(Q, K, P, PS, scale);

    // idx 3) out = (1/rowsum) * (P @ V); rowsum inverses from PS in-prologue
    dim3 gp(DD / TN, SS / TM, BB);
    pv_gemm<<<gp, NTHREADS, DSM_BYTES>>>(P, Vt, PS, out);
}

// round 17
// speedup vs baseline: 1.2909x; 1.0082x over previous
#include <cuda_runtime.h>
#include <cstdint>
#include <math.h>

#define BB 4
#define SS 2048
#define DD 1024

#define TM 128
#define TN 64
#define TK 32
#define NTHREADS 256
#define STAGES 3
#define STAGE_BYTES 24576            // A fp32 16K | B fp32 8K
#define DSM_BYTES (STAGES * STAGE_BYTES + 1024)

// 128x128 scores tile variant
#define STAGE_BYTES2 32768           // A 16K | B 16K
#define DSM_BYTES2 (STAGES * STAGE_BYTES2 + 1024)
#define LIVE_TILES2 136              // 16*17/2 tiles of 128x128 per batch

// ---------------------------------------------------------------------------
// Scratch (__device__ globals; zero-initialized at module load — PS relies on
// this: slots >= 32 are never written by this build and read as 0).
// ---------------------------------------------------------------------------
__device__ float g_X [(size_t)BB * SS * DD];          // x (tf32)      32 MB
__device__ float g_Wt[3][(size_t)DD * DD];            // W^T (tf32)    12 MB
__device__ float g_Q [(size_t)BB * SS * DD];          // Q (tf32)      32 MB
__device__ float g_K [(size_t)BB * SS * DD];          // K (tf32)      32 MB
__device__ float g_Vt[(size_t)BB * SS * DD];          // V^T (tf32)    32 MB
__device__ float g_P [(size_t)BB * SS * SS];          // exp-scores     64 MB
__device__ float g_PS[(size_t)BB * SS * 64];          // row partials    2 MB

// ---------------------------------------------------------------------------
// Helpers
// ---------------------------------------------------------------------------
__device__ __forceinline__ uint32_t smem_u32(const void* p) {
    uint32_t a;
    asm("{ .reg .u64 t; cvta.to.shared.u64 t, %1; cvt.u32.u64 %0, t; }"
        : "=r"(a) : "l"(p));
    return a;
}

__device__ __forceinline__ uint32_t tf32r(float f) {
    uint32_t r;
    asm("cvt.rna.tf32.f32 %0, %1;" : "=r"(r) : "f"(f));
    return r;
}

#define LDSM4(r, a)                                                        \
    asm volatile("ldmatrix.sync.aligned.m8n8.x4.shared.b16 "               \
                 "{%0,%1,%2,%3}, [%4];"                                    \
                 : "=r"((r)[0]), "=r"((r)[1]), "=r"((r)[2]), "=r"((r)[3])  \
                 : "r"(a))

#define MMATF32(d, a, b0, b1)                                              \
    asm volatile("mma.sync.aligned.m16n8k8.row.col.f32.tf32.tf32.f32 "     \
                 "{%0,%1,%2,%3},{%4,%5,%6,%7},{%8,%9},{%0,%1,%2,%3};"      \
                 : "+f"((d)[0]), "+f"((d)[1]), "+f"((d)[2]), "+f"((d)[3])  \
                 : "r"((a)[0]), "r"((a)[1]), "r"((a)[2]), "r"((a)[3]),     \
                   "r"(b0), "r"(b1))

#define CPA16(dst, src)                                                    \
    asm volatile("cp.async.cg.shared.global [%0], [%1], 16;"               \
                 :: "r"(dst), "l"(src))
#define CPA_COMMIT()  asm volatile("cp.async.commit_group;" ::: "memory")
#define CPA_WAIT1()   asm volatile("cp.async.wait_group 1;" ::: "memory")

// ===========================================================================
// 128x64 GEMM body (R16-proven: 3 stages, 3 CTAs/SM, warp tile 32x32).
// ===========================================================================
struct GemmCtx {
    uint32_t sbase;
    uint32_t aoffs;
    const float* gA;
    const float* gB;
    int a32, b32;
    uint32_t aSw[2], bSw[2];
    uint32_t hb;
};

__device__ __forceinline__ void gemm_setup(GemmCtx& cx, uint32_t sbase,
                                           const float* A, int lda, int m0,
                                           const float* B, int ldb, int n0,
                                           int tid, int lane, int wid)
{
    cx.sbase = sbase;
    const int wm = (wid & 3) * 32;
    const int wn = (wid >> 2) * 32;

    const int arow = tid >> 3, cu = tid & 7;
    cx.aoffs = ((uint32_t)arow * 128u + (uint32_t)cu * 16u)
               ^ (((uint32_t)(arow & 7)) << 4);
    cx.gA = A + (long long)(m0 + arow) * lda + cu * 4;
    cx.gB = B + (long long)(n0 + arow) * ldb + cu * 4;
    cx.a32 = 32 * lda;
    cx.b32 = 32 * ldb;

    const int fr = lane & 15;
    cx.hb = (uint32_t)(lane >> 4) * 16u;
#pragma unroll
    for (int mf = 0; mf < 2; mf++) {
        int row = wm + 16 * mf + fr;
        cx.aSw[mf] = (uint32_t)row * 128u ^ (((uint32_t)(row & 7)) << 4);
    }
#pragma unroll
    for (int g = 0; g < 2; g++) {
        int row = wn + 16 * g + fr;
        cx.bSw[g] = 16384u + ((uint32_t)row * 128u ^ (((uint32_t)(row & 7)) << 4));
    }
}

__device__ __forceinline__ void gemm_issue(const GemmCtx& cx, int sidx, int k0)
{
    const uint32_t sb_ = cx.sbase + (uint32_t)sidx * STAGE_BYTES;
    CPA16(sb_ + cx.aoffs,          cx.gA + k0);
    CPA16(sb_ + cx.aoffs +  4096u, cx.gA + k0 + cx.a32);
    CPA16(sb_ + cx.aoffs +  8192u, cx.gA + k0 + 2 * cx.a32);
    CPA16(sb_ + cx.aoffs + 12288u, cx.gA + k0 + 3 * cx.a32);
    CPA16(sb_ + 16384u + cx.aoffs,         cx.gB + k0);
    CPA16(sb_ + 16384u + cx.aoffs + 4096u, cx.gB + k0 + cx.b32);
}

__device__ __forceinline__ void gemm_mainloop(const GemmCtx& cx, int KB,
                                              float acc[2][4][4])
{
#pragma unroll
    for (int s = 0; s < STAGES - 1; s++) {
        if (s < KB) gemm_issue(cx, s, s * TK);
        CPA_COMMIT();
    }

    int sidx_c = 0;
    int sidx_w = STAGES - 1;
    for (int kb = 0; kb < KB; kb++) {
        CPA_WAIT1();
        __syncthreads();

        const uint32_t buf = cx.sbase + (uint32_t)sidx_c * STAGE_BYTES;
        if (++sidx_c == STAGES) sidx_c = 0;

#pragma unroll
        for (int kblk = 0; kblk < 4; kblk++) {
            const uint32_t kc = (uint32_t)(kblk * 32) + cx.hb;
            uint32_t a[2][4], b[2][4];
            LDSM4(a[0], buf + (cx.aSw[0] ^ kc));
            LDSM4(a[1], buf + (cx.aSw[1] ^ kc));
            LDSM4(b[0], buf + (cx.bSw[0] ^ kc));
            LDSM4(b[1], buf + (cx.bSw[1] ^ kc));
#pragma unroll
            for (int mf = 0; mf < 2; mf++)
#pragma unroll
                for (int g = 0; g < 2; g++)
#pragma unroll
                    for (int s = 0; s < 2; s++)
                        MMATF32(acc[mf][2 * g + s], a[mf], b[g][s], b[g][s + 2]);

            if (kblk == 0) {
                if (kb + STAGES - 1 < KB)
                    gemm_issue(cx, sidx_w, (kb + STAGES - 1) * TK);
                CPA_COMMIT();
                if (++sidx_w == STAGES) sidx_w = 0;
            }
        }
    }
}

// ---------------------------------------------------------------------------
// Scores kernel: 128x128 tile (warp tile 32x64), 2 CTAs/SM, compact
// triangular grid of 136 tiles/batch, heavy rows first.
// P[q,k] = tf32r(exp(scale*QK^T)) for k<=q, 0 on masked elems of live tiles.
// Partial row sums (of rounded values) -> PS slots [row][chunk64], chunk64 =
// (n0+wn)/64 in 0..31; slots 32..63 never written (zero from static init).
// ---------------------------------------------------------------------------
__global__ void __launch_bounds__(NTHREADS, 2)
scores_gemm(const float* __restrict__ Q, const float* __restrict__ K,
            float* __restrict__ P, float* __restrict__ PS, float scale)
{
    // triangular decode (row-major lower triangle), heavy rows first
    const int t = LIVE_TILES2 - 1 - blockIdx.x;          // 0..135
    int by = (int)((sqrtf(8.0f * t + 1.0f) - 1.0f) * 0.5f);
    if ((by + 1) * (by + 2) / 2 <= t) by++;
    if (by * (by + 1) / 2 > t) by--;
    const int bx = t - by * (by + 1) / 2;                // 0..by

    const int m0 = by * 128;
    const int n0 = bx * 128;

    extern __shared__ char dsm[];
    const uint32_t sbase = (smem_u32(dsm) + 1023u) & ~1023u;

    const long long z = blockIdx.z;
    const float* A = Q + (long long)z * SS * DD;
    const float* B = K + (long long)z * SS * DD;

    const int tid  = threadIdx.x;
    const int lane = tid & 31;
    const int wid  = tid >> 5;
    const int wm = (wid & 3) * 32;
    const int wn = (wid >> 2) * 64;

    // cp.async: A and B both 128 rows x 128B; 4 tasks each per thread
    const int arow = tid >> 3, cu = tid & 7;
    const uint32_t aoffs = ((uint32_t)arow * 128u + (uint32_t)cu * 16u)
                           ^ (((uint32_t)(arow & 7)) << 4);
    const float* gA = A + (long long)(m0 + arow) * DD + cu * 4;
    const float* gB = B + (long long)(n0 + arow) * DD + cu * 4;
    const int r32 = 32 * DD;

    const int fr = lane & 15;
    const uint32_t hb = (uint32_t)(lane >> 4) * 16u;
    uint32_t aSw[2], bSw[4];
#pragma unroll
    for (int mf = 0; mf < 2; mf++) {
        int row = wm + 16 * mf + fr;
        aSw[mf] = (uint32_t)row * 128u ^ (((uint32_t)(row & 7)) << 4);
    }
#pragma unroll
    for (int g = 0; g < 4; g++) {
        int row = wn + 16 * g + fr;
        bSw[g] = 16384u + ((uint32_t)row * 128u ^ (((uint32_t)(row & 7)) << 4));
    }

    float acc[2][8][4];
#pragma unroll
    for (int mf = 0; mf < 2; mf++)
#pragma unroll
        for (int nf = 0; nf < 8; nf++)
#pragma unroll
            for (int j = 0; j < 4; j++) acc[mf][nf][j] = 0.0f;

#define ISSUE2(sidx, k0)                                                   \
    do {                                                                   \
        const uint32_t sb_ = sbase + (uint32_t)(sidx) * STAGE_BYTES2;      \
        CPA16(sb_ + aoffs,          gA + (k0));                            \
        CPA16(sb_ + aoffs +  4096u, gA + (k0) + r32);                      \
        CPA16(sb_ + aoffs +  8192u, gA + (k0) + 2 * r32);                  \
        CPA16(sb_ + aoffs + 12288u, gA + (k0) + 3 * r32);                  \
        CPA16(sb_ + 16384u + aoffs,          gB + (k0));                   \
        CPA16(sb_ + 16384u + aoffs +  4096u, gB + (k0) + r32);             \
        CPA16(sb_ + 16384u + aoffs +  8192u, gB + (k0) + 2 * r32);         \
        CPA16(sb_ + 16384u + aoffs + 12288u, gB + (k0) + 3 * r32);         \
    } while (0)

#pragma unroll
    for (int s = 0; s < STAGES - 1; s++) {
        ISSUE2(s, s * TK);
        CPA_COMMIT();
    }

    int sidx_c = 0;
    int sidx_w = STAGES - 1;
    const int KB = DD / TK;
    for (int kb = 0; kb < KB; kb++) {
        CPA_WAIT1();
        __syncthreads();

        const uint32_t buf = sbase + (uint32_t)sidx_c * STAGE_BYTES2;
        if (++sidx_c == STAGES) sidx_c = 0;

#pragma unroll
        for (int kblk = 0; kblk < 4; kblk++) {
            const uint32_t kc = (uint32_t)(kblk * 32) + hb;
            uint32_t a[2][4], b[4][4];
            LDSM4(a[0], buf + (aSw[0] ^ kc));
            LDSM4(a[1], buf + (aSw[1] ^ kc));
#pragma unroll
            for (int g = 0; g < 4; g++)
                LDSM4(b[g], buf + (bSw[g] ^ kc));
#pragma unroll
            for (int mf = 0; mf < 2; mf++)
#pragma unroll
                for (int g = 0; g < 4; g++)
#pragma unroll
                    for (int s = 0; s < 2; s++)
                        MMATF32(acc[mf][2 * g + s], a[mf], b[g][s], b[g][s + 2]);

            if (kblk == 0) {
                if (kb + STAGES - 1 < KB)
                    ISSUE2(sidx_w, (kb + STAGES - 1) * TK);
                CPA_COMMIT();
                if (++sidx_w == STAGES) sidx_w = 0;
            }
        }
    }
#undef ISSUE2

    // ---- exp epilogue ----
    const int gq = lane >> 2, tt = lane & 3;
    float* Pz = P + (long long)z * SS * SS;

    float psum[4] = {0.0f, 0.0f, 0.0f, 0.0f};
#pragma unroll
    for (int mf = 0; mf < 2; mf++) {
        const int r0 = m0 + wm + 16 * mf + gq;
#pragma unroll
        for (int nf = 0; nf < 8; nf++) {
            const int col = n0 + wn + 8 * nf + 2 * tt;
            float e00 = (col     <= r0    ) ? __expf(acc[mf][nf][0] * scale) : 0.0f;
            float e01 = (col + 1 <= r0    ) ? __expf(acc[mf][nf][1] * scale) : 0.0f;
            float e10 = (col     <= r0 + 8) ? __expf(acc[mf][nf][2] * scale) : 0.0f;
            float e11 = (col + 1 <= r0 + 8) ? __expf(acc[mf][nf][3] * scale) : 0.0f;
            e00 = __uint_as_float(tf32r(e00));
            e01 = __uint_as_float(tf32r(e01));
            e10 = __uint_as_float(tf32r(e10));
            e11 = __uint_as_float(tf32r(e11));
            float2 o0, o1;
            o0.x = e00; o0.y = e01;
            o1.x = e10; o1.y = e11;
            *reinterpret_cast<float2*>(Pz + (long long)r0 * SS + col)       = o0;
            *reinterpret_cast<float2*>(Pz + (long long)(r0 + 8) * SS + col) = o1;
            psum[mf * 2]     += e00 + e01;
            psum[mf * 2 + 1] += e10 + e11;
        }
    }
#pragma unroll
    for (int off = 1; off <= 2; off <<= 1)
#pragma unroll
        for (int i = 0; i < 4; i++)
            psum[i] += __shfl_xor_sync(0xFFFFFFFFu, psum[i], off);

    if (tt == 0) {
        const int slot = bx * 2 + (wid >> 2);   // 64-col chunk index, 0..31
        const size_t rb = (size_t)z * SS;
        const int rbase = m0 + wm + gq;
        PS[(rb + rbase)      * 64 + slot] = psum[0];
        PS[(rb + rbase + 8)  * 64 + slot] = psum[1];
        PS[(rb + rbase + 16) * 64 + slot] = psum[2];
        PS[(rb + rbase + 24) * 64 + slot] = psum[3];
    }
}

// ---------------------------------------------------------------------------
// P@V kernel (R16): 128x64 tile, per-q K limit, rowsum-inverse prologue
// (slot-split over tt + butterfly; deterministic).
// ---------------------------------------------------------------------------
__global__ void __launch_bounds__(NTHREADS, 3)
pv_gemm(const float* __restrict__ P, const float* __restrict__ Vt,
        const float* __restrict__ PS, float* __restrict__ Out)
{
    const int by = gridDim.y - 1 - blockIdx.y;     // heavy rows first
    const int m0 = by * TM;
    const int n0 = blockIdx.x * TN;

    extern __shared__ char dsm[];
    const uint32_t sbase = (smem_u32(dsm) + 1023u) & ~1023u;

    const long long z = blockIdx.z;
    const float* A = P  + (long long)z * SS * SS;
    const float* B = Vt + (long long)z * SS * DD;

    const int KB = ((by + 1) * TM) / TK;

    const int tid  = threadIdx.x;
    const int lane = tid & 31;
    const int wid  = tid >> 5;

    const int wm = (wid & 3) * 32;
    const int gq = lane >> 2, tt = lane & 3;
    float inv[4];
    {
        const size_t rb = (size_t)z * SS;
        const int rbase = m0 + wm + gq;
#pragma unroll
        for (int r = 0; r < 4; r++) {
            const float4* ps = reinterpret_cast<const float4*>(
                PS + (rb + rbase + 8 * r) * 64) + tt * 4;
            float s = 0.0f;
#pragma unroll
            for (int j = 0; j < 4; j++) {
                float4 v = ps[j];
                s += (v.x + v.y) + (v.z + v.w);
            }
            s += __shfl_xor_sync(0xFFFFFFFFu, s, 1);
            s += __shfl_xor_sync(0xFFFFFFFFu, s, 2);
            inv[r] = 1.0f / s;
        }
    }

    GemmCtx cx;
    gemm_setup(cx, sbase, A, SS, m0, B, SS, n0, tid, lane, wid);

    float acc[2][4][4];
#pragma unroll
    for (int mf = 0; mf < 2; mf++)
#pragma unroll
        for (int nf = 0; nf < 4; nf++)
#pragma unroll
            for (int j = 0; j < 4; j++) acc[mf][nf][j] = 0.0f;

    gemm_mainloop(cx, KB, acc);

    const int wn = (wid >> 2) * 32;
    float* C = Out + (long long)z * SS * DD;
#pragma unroll
    for (int mf = 0; mf < 2; mf++) {
        const int r0 = m0 + wm + 16 * mf + gq;
        const float inv0 = inv[mf * 2];
        const float inv1 = inv[mf * 2 + 1];
#pragma unroll
        for (int nf = 0; nf < 4; nf++) {
            const int col = n0 + wn + 8 * nf + 2 * tt;
            float2 o0, o1;
            o0.x = acc[mf][nf][0] * inv0;
            o0.y = acc[mf][nf][1] * inv0;
            o1.x = acc[mf][nf][2] * inv1;
            o1.y = acc[mf][nf][3] * inv1;
            *reinterpret_cast<float2*>(C + (long long)r0 * DD + col)       = o0;
            *reinterpret_cast<float2*>(C + (long long)(r0 + 8) * DD + col) = o1;
        }
    }
}

// ---------------------------------------------------------------------------
// Fused QKV kernel (R16): z selects {Wq,Wk,Wv}; V emitted transposed.
// ---------------------------------------------------------------------------
__global__ void __launch_bounds__(NTHREADS, 3)
qkv_gemm(const float* __restrict__ X, const float* __restrict__ Wt,
         float* __restrict__ Qo, float* __restrict__ Ko, float* __restrict__ VtO)
{
    const int m0 = blockIdx.y * TM;
    const int n0 = blockIdx.x * TN;
    const int z  = blockIdx.z;

    extern __shared__ char dsm[];
    const uint32_t sbase = (smem_u32(dsm) + 1023u) & ~1023u;

    const float* B = Wt + (size_t)z * DD * DD;

    const int tid  = threadIdx.x;
    const int lane = tid & 31;
    const int wid  = tid >> 5;

    GemmCtx cx;
    gemm_setup(cx, sbase, X, DD, m0, B, DD, n0, tid, lane, wid);

    float acc[2][4][4];
#pragma unroll
    for (int mf = 0; mf < 2; mf++)
#pragma unroll
        for (int nf = 0; nf < 4; nf++)
#pragma unroll
            for (int j = 0; j < 4; j++) acc[mf][nf][j] = 0.0f;

    gemm_mainloop(cx, DD / TK, acc);

    const int wm = (wid & 3) * 32;
    const int wn = (wid >> 2) * 32;
    const int gq = lane >> 2, t = lane & 3;

    if (z < 2) {
        float* C = (z == 0) ? Qo : Ko;
#pragma unroll
        for (int mf = 0; mf < 2; mf++) {
#pragma unroll
            for (int nf = 0; nf < 4; nf++) {
                const int r0  = m0 + wm + 16 * mf + gq;
                const int col = n0 + wn + 8 * nf + 2 * t;
                float2 o0, o1;
                o0.x = __uint_as_float(tf32r(acc[mf][nf][0]));
                o0.y = __uint_as_float(tf32r(acc[mf][nf][1]));
                o1.x = __uint_as_float(tf32r(acc[mf][nf][2]));
                o1.y = __uint_as_float(tf32r(acc[mf][nf][3]));
                *reinterpret_cast<float2*>(C + (long long)r0 * DD + col)       = o0;
                *reinterpret_cast<float2*>(C + (long long)(r0 + 8) * DD + col) = o1;
            }
        }
    } else {
        __syncthreads();
        float* ts = reinterpret_cast<float*>(dsm +
                        (size_t)(sbase - smem_u32(dsm)));
#pragma unroll
        for (int mf = 0; mf < 2; mf++) {
#pragma unroll
            for (int nf = 0; nf < 4; nf++) {
                const int m_ = wm + 16 * mf + gq;
                const int n_ = wn + 8 * nf + 2 * t;
                ts[n_ * 132 + m_]             = acc[mf][nf][0];
                ts[(n_ + 1) * 132 + m_]       = acc[mf][nf][1];
                ts[n_ * 132 + m_ + 8]         = acc[mf][nf][2];
                ts[(n_ + 1) * 132 + m_ + 8]   = acc[mf][nf][3];
            }
        }
        __syncthreads();
        const int vr = tid >> 2;
        const int vc = tid & 3;
        const int b  = m0 >> 11;
        const int s0 = m0 & (SS - 1);
        float* dst = VtO + (size_t)b * SS * DD
                   + (size_t)(n0 + vr) * SS + s0 + vc * 32;
#pragma unroll
        for (int i = 0; i < 8; i++) {
            float4 v = *reinterpret_cast<const float4*>(
                ts + vr * 132 + vc * 32 + i * 4);
            v.x = __uint_as_float(tf32r(v.x));
            v.y = __uint_as_float(tf32r(v.y));
            v.z = __uint_as_float(tf32r(v.z));
            v.w = __uint_as_float(tf32r(v.w));
            *reinterpret_cast<float4*>(dst + i * 4) = v;
        }
    }
}

// ---------------------------------------------------------------------------
// Prep kernel: X-convert with 4-deep MLP (4 independent float4 per thread),
// then W transposes.
// ---------------------------------------------------------------------------
#define XN4   (BB * SS * DD / 4)               // 2M float4
#define XCB   (XN4 / 1024)                     // 2048 blocks, 1024 f4/block
#define WTB   (3 * (DD / 32) * (DD / 32))      // 3072 blocks

__global__ void __launch_bounds__(256)
prep_kernel(const float* __restrict__ x, float* __restrict__ X,
            const float* __restrict__ Wq, const float* __restrict__ Wk,
            const float* __restrict__ Wv, float* __restrict__ WtBase)
{
    __shared__ float t[32][33];
    const int b = blockIdx.x;
    const int tid = threadIdx.x;

    if (b < XCB) {
        const int base = b * 1024 + tid;
        float4 v[4];
#pragma unroll
        for (int i = 0; i < 4; i++)
            v[i] = reinterpret_cast<const float4*>(x)[base + i * 256];
#pragma unroll
        for (int i = 0; i < 4; i++) {
            v[i].x = __uint_as_float(tf32r(v[i].x));
            v[i].y = __uint_as_float(tf32r(v[i].y));
            v[i].z = __uint_as_float(tf32r(v[i].z));
            v[i].w = __uint_as_float(tf32r(v[i].w));
            reinterpret_cast<float4*>(X)[base + i * 256] = v[i];
        }
    } else {
        const int idx = b - XCB;
        const int z   = idx >> 10;
        const int rem = idx & 1023;
        const int bx  = rem & 31;
        const int byy = rem >> 5;
        const float* in = (z == 0) ? Wq : (z == 1) ? Wk : Wv;
        float* out = WtBase + (size_t)z * DD * DD;
        const int c0 = bx * 32, r0 = byy * 32;
        const int tx = tid & 31, ty = tid >> 5;
#pragma unroll
        for (int j = ty; j < 32; j += 8)
            t[j][tx] = in[(long long)(r0 + j) * DD + c0 + tx];
        __syncthreads();
#pragma unroll
        for (int j = ty; j < 32; j += 8)
            out[(long long)(c0 + j) * DD + r0 + tx] =
                __uint_as_float(tf32r(t[tx][j]));
    }
}

// ---------------------------------------------------------------------------
// Launch sequence (graph-capturable: kernel launches only).
// prep(0), QKV+Vt(1), scores128+exp(2), P@V+rowinv(3).
// ---------------------------------------------------------------------------
extern "C" void kernel_launch(void* const* d_in, const int* in_sizes, int n_in,
                              void* d_out, int out_size)
{
    const float* x  = (const float*)d_in[0];
    const float* Wq = (const float*)d_in[1];
    const float* Wk = (const float*)d_in[2];
    const float* Wv = (const float*)d_in[3];
    float* out = (float*)d_out;

    float *X, *Wt, *Q, *K, *Vt, *P, *PS;
    cudaGetSymbolAddress((void**)&X,  g_X);
    cudaGetSymbolAddress((void**)&Wt, g_Wt);
    cudaGetSymbolAddress((void**)&Q,  g_Q);
    cudaGetSymbolAddress((void**)&K,  g_K);
    cudaGetSymbolAddress((void**)&Vt, g_Vt);
    cudaGetSymbolAddress((void**)&P,  g_P);
    cudaGetSymbolAddress((void**)&PS, g_PS);

    cudaFuncSetAttribute(qkv_gemm,
                         cudaFuncAttributeMaxDynamicSharedMemorySize, DSM_BYTES);
    cudaFuncSetAttribute(scores_gemm,
                         cudaFuncAttributeMaxDynamicSharedMemorySize, DSM_BYTES2);
    cudaFuncSetAttribute(pv_gemm,
                         cudaFuncAttributeMaxDynamicSharedMemorySize, DSM_BYTES);

    const float scale = 0.03125f;     // 1024^-0.5

    // idx 0) prep: x -> tf32 (MLP-4), W -> W^T
    prep_kernel<<<XCB + WTB, 256>>>(x, X, Wq, Wk, Wv, Wt);

    // idx 1) Fused QKV projection; V emitted transposed (per-batch [DD][SS])
    dim3 gq(DD / TN, (BB * SS) / TM, 3);
    qkv_gemm<<<gq, NTHREADS, DSM_BYTES>>>(X, Wt, Q, K, Vt);

    // idx 2) P = exp(scale * Q K^T), masked; 128x128 compact triangular grid
    dim3 gs(LIVE_TILES2, 1, BB);
    scores_gemm<<<gs, NTHREADS, DSM_BYTES2>>>(Q, K, P, PS, scale);

    // idx 3) out = (1/rowsum) * (P @ V)
    dim3 gp(DD / TN, SS / TM, BB);
    pv_gemm<<<gp, NTHREADS, DSM_BYTES>>>(P, Vt, PS, out);
}